// round 13
// baseline (speedup 1.0000x reference)
#include <cuda_runtime.h>
#include <cuda_fp16.h>
#include <math_constants.h>
#include <cstdint>

#define NTOK 4096      // B*S
#define DIM  1024
#define HEADS 16
#define HDIM 64
#define SEQ  2048
#define BATCH 2

// Scratch (allocation-free requirement -> __device__ globals), all fp16
__device__ __half g_xh[NTOK * DIM];
__device__ __half g_wh[4 * DIM * DIM];    // fp16 Wq,Wk,Wv,Wo (natural [K][N])
__device__ __half g_qh[NTOK * DIM];
__device__ __half g_kh[NTOK * DIM];
__device__ __half g_vh[NTOK * DIM];
__device__ __half g_ctxh[NTOK * DIM];

// ===========================================================================
// Helpers
// ===========================================================================
__device__ __forceinline__ float ex2f(float x) {
    float y;
    asm("ex2.approx.ftz.f32 %0, %1;" : "=f"(y) : "f"(x));
    return y;
}

#define CP_ASYNC16(smem_addr, gmem_ptr) \
    asm volatile("cp.async.cg.shared.global [%0], [%1], 16;" \
                 :: "r"((uint32_t)(smem_addr)), "l"(gmem_ptr) : "memory")
#define CP_COMMIT() asm volatile("cp.async.commit_group;" ::: "memory")
#define CP_WAIT(n)  asm volatile("cp.async.wait_group %0;" :: "n"(n) : "memory")

__device__ __forceinline__ uint32_t smem_u32(const void* p) {
    uint32_t a;
    asm("{ .reg .u64 t; cvta.to.shared.u64 t, %1; cvt.u32.u64 %0, t; }"
        : "=r"(a) : "l"(p));
    return a;
}

#define LDSM_X4(r0, r1, r2, r3, addr) \
    asm volatile("ldmatrix.sync.aligned.m8n8.x4.shared.b16 {%0,%1,%2,%3}, [%4];" \
                 : "=r"(r0), "=r"(r1), "=r"(r2), "=r"(r3) : "r"(addr))

#define LDSM_X4_T(r0, r1, r2, r3, addr) \
    asm volatile("ldmatrix.sync.aligned.m8n8.x4.trans.shared.b16 {%0,%1,%2,%3}, [%4];" \
                 : "=r"(r0), "=r"(r1), "=r"(r2), "=r"(r3) : "r"(addr))

// mma m16n8k16 fp16 in, fp32 accum
__device__ __forceinline__ void mma_f16(
    float* d, const uint32_t* a, const uint32_t* b)
{
    asm volatile(
        "mma.sync.aligned.m16n8k16.row.col.f32.f16.f16.f32 "
        "{%0,%1,%2,%3}, {%4,%5,%6,%7}, {%8,%9}, {%0,%1,%2,%3};"
        : "+f"(d[0]), "+f"(d[1]), "+f"(d[2]), "+f"(d[3])
        : "r"(a[0]), "r"(a[1]), "r"(a[2]), "r"(a[3]),
          "r"(b[0]), "r"(b[1]));
}

// ===========================================================================
// fp16 GEMM (exact R9/R12 version — unchanged).
// ===========================================================================
#define GDIM 1024
#define BKH 64
#define ASTRH 72
#define BSTRH 136
#define A_STH (128 * ASTRH)          // 9216 halves
#define B_STH (BKH * BSTRH)          // 8704 halves
#define STH   (A_STH + B_STH)        // 17920 halves per stage
#define NSTG  3
#define GEMM_SMEM_BYTES (NSTG * STH * 2)   // 107520 B

__global__ void __launch_bounds__(256, 2) gemm_h_kernel(
    const __half* __restrict__ A,
    const __half* __restrict__ W0, const __half* __restrict__ W1,
    const __half* __restrict__ W2,
    const float* __restrict__ b0p, const float* __restrict__ b1p,
    const float* __restrict__ b2p,
    void* __restrict__ C0, void* __restrict__ C1, void* __restrict__ C2,
    int out_half)
{
    extern __shared__ __align__(16) __half smh[];

    const int z = blockIdx.z;
    const __half* W    = (z == 0) ? W0 : (z == 1) ? W1 : W2;
    const float*  bias = (z == 0) ? b0p : (z == 1) ? b1p : b2p;
    void*         Cv   = (z == 0) ? C0 : (z == 1) ? C1 : C2;

    const int tid  = threadIdx.x;
    const int wid  = tid >> 5;
    const int lane = tid & 31;
    const int g    = lane >> 2;
    const int t    = lane & 3;
    const int lrow = lane & 7;
    const int sub  = lane >> 3;      // 0..3
    const int wm   = wid >> 1;       // 0..3
    const int wn   = wid & 1;        // 0..1

    const int brow = blockIdx.y * 128;
    const int bcol = blockIdx.x * 128;

    const uint32_t smu = smem_u32(smh);

    const int arow_l = wm * 32 + lrow + ((sub & 1) << 3);
    const int akoff  = (sub >> 1) << 3;
    const int btrow  = lrow + ((sub & 1) << 3);
    const int bncol  = (sub >> 1) << 3;

    const int alr = tid >> 3;
    const int alc = (tid & 7) * 8;
    const __half* Asrc = A + (size_t)(brow + alr) * GDIM + alc;
    const int blr = tid >> 4;
    const int blc = (tid & 15) * 8;

    auto load_stage = [&](int s, int kt) {
        const int k0 = kt * BKH;
        const uint32_t abase = smu + (uint32_t)(s * STH) * 2u;
        const uint32_t bbase = abase + (uint32_t)A_STH * 2u;
#pragma unroll
        for (int i = 0; i < 4; i++) {
            const int ra = alr + i * 32;
            CP_ASYNC16(abase + (uint32_t)(ra * ASTRH + alc) * 2u,
                       Asrc + (size_t)(i * 32) * GDIM + k0);
            const int rb = blr + i * 16;
            CP_ASYNC16(bbase + (uint32_t)(rb * BSTRH + blc) * 2u,
                       W + (size_t)(k0 + rb) * GDIM + bcol + blc);
        }
        CP_COMMIT();
    };

    float acc[2][8][4];
#pragma unroll
    for (int mi = 0; mi < 2; mi++)
#pragma unroll
        for (int ni = 0; ni < 8; ni++)
#pragma unroll
            for (int c = 0; c < 4; c++) acc[mi][ni][c] = 0.f;

    load_stage(0, 0);
    load_stage(1, 1);

    const int NKT = GDIM / BKH;   // 16
    for (int kt = 0; kt < NKT; ++kt) {
        const int cur = kt % NSTG;
        CP_WAIT(1);
        __syncthreads();

        const uint32_t aBase = smu + (uint32_t)(cur * STH) * 2u;
        const uint32_t bBase = aBase + (uint32_t)A_STH * 2u;

#pragma unroll
        for (int ks = 0; ks < 4; ks++) {
            uint32_t af[2][4];
#pragma unroll
            for (int mi = 0; mi < 2; mi++) {
                const uint32_t a = aBase +
                    (uint32_t)((arow_l + mi * 16) * ASTRH + ks * 16 + akoff) * 2u;
                LDSM_X4(af[mi][0], af[mi][1], af[mi][2], af[mi][3], a);
            }
            uint32_t bf[8][2];
#pragma unroll
            for (int pi = 0; pi < 4; pi++) {
                const uint32_t a = bBase +
                    (uint32_t)((ks * 16 + btrow) * BSTRH +
                               wn * 64 + pi * 16 + bncol) * 2u;
                uint32_t r0, r1, r2, r3;
                LDSM_X4_T(r0, r1, r2, r3, a);
                bf[2 * pi][0] = r0; bf[2 * pi][1] = r1;
                bf[2 * pi + 1][0] = r2; bf[2 * pi + 1][1] = r3;
            }
#pragma unroll
            for (int mi = 0; mi < 2; mi++)
#pragma unroll
                for (int ni = 0; ni < 8; ni++)
                    mma_f16(acc[mi][ni], af[mi], bf[ni]);
        }

        if (kt + 2 < NKT) load_stage((kt + 2) % NSTG, kt + 2);
    }

    // Epilogue
#pragma unroll
    for (int ni = 0; ni < 8; ni++) {
        const int col = bcol + wn * 64 + ni * 8 + t * 2;
        const float2 bv = *reinterpret_cast<const float2*>(&bias[col]);
#pragma unroll
        for (int mi = 0; mi < 2; mi++) {
            const int r0 = brow + wm * 32 + mi * 16 + g;
            float2 v0, v1;
            v0.x = acc[mi][ni][0] + bv.x;
            v0.y = acc[mi][ni][1] + bv.y;
            v1.x = acc[mi][ni][2] + bv.x;
            v1.y = acc[mi][ni][3] + bv.y;
            if (out_half) {
                __half* C = (__half*)Cv;
                *reinterpret_cast<__half2*>(&C[(size_t)r0 * GDIM + col]) =
                    __floats2half2_rn(v0.x, v0.y);
                *reinterpret_cast<__half2*>(&C[(size_t)(r0 + 8) * GDIM + col]) =
                    __floats2half2_rn(v1.x, v1.y);
            } else {
                float* C = (float*)Cv;
                *reinterpret_cast<float2*>(&C[(size_t)r0 * GDIM + col])       = v0;
                *reinterpret_cast<float2*>(&C[(size_t)(r0 + 8) * GDIM + col]) = v1;
            }
        }
    }
}

// ===========================================================================
// Prep (z-split, unchanged)
// ===========================================================================
#define PREP_CHUNK (DIM * DIM / 2)   // 524288 half2 per W

__global__ void f2h_multi_kernel(
    const float2* __restrict__ x,
    const float2* __restrict__ Wq, const float2* __restrict__ Wk,
    const float2* __restrict__ Wv, const float2* __restrict__ Wo,
    __half2* __restrict__ xh, __half2* __restrict__ wh)
{
    const int z = blockIdx.z;
    const int i = blockIdx.x * blockDim.x + threadIdx.x;
    if (z < 4) {
        const float2* src = (z == 0) ? Wq : (z == 1) ? Wk : (z == 2) ? Wv : Wo;
        float2 v = src[i];
        wh[(size_t)z * PREP_CHUNK + i] = __floats2half2_rn(v.x, v.y);
    } else {
#pragma unroll
        for (int j = 0; j < 4; j++) {
            const size_t idx = (size_t)i + (size_t)j * PREP_CHUNK;
            float2 v = x[idx];
            xh[idx] = __floats2half2_rn(v.x, v.y);
        }
    }
}

// ===========================================================================
// fp16 flash attention (R12 structure; softmax exp in fp16x2:
// args packed via cvt.rn.f16x2.f32, one ex2.approx.f16x2 per half2.
// Same half2 P feeds PV mma AND the fp32 l-sum -> num/denom consistent).
// ===========================================================================
#define QSTR 72
#define SP_OFF   (128 * QSTR)
#define SK_OFF   (2 * 128 * QSTR)
#define KVBUF    (128 * QSTR)                 // one 128-key buffer
#define SV_OFF   (SK_OFF + 2 * KVBUF)
#define ATTN_SMEM_BYTES ((2 * 128 * QSTR + 4 * KVBUF) * 2)   // 110592 B

__global__ void __launch_bounds__(256, 2) attn_h_kernel(
    const __half* __restrict__ Q, const __half* __restrict__ K,
    const __half* __restrict__ V, __half* __restrict__ O)
{
    extern __shared__ __align__(16) __half smh[];
    const uint32_t smu = smem_u32(smh);
    __half* sP = smh + SP_OFF;

    const int tid  = threadIdx.x;
    const int wid  = tid >> 5;
    const int lane = tid & 31;
    const int g    = lane >> 2;
    const int t    = lane & 3;
    const int lrow = lane & 7;
    const int sub  = lane >> 3;
    const int wm   = wid * 16;

    const int q0 = blockIdx.x * 128;
    const int h  = blockIdx.y;
    const int b  = blockIdx.z;
    const size_t rowbase = (size_t)b * SEQ;
    const int colbase = h * HDIM;

    const float cscale = 0.125f * 1.4426950408889634f;  // 1/sqrt(64)*log2(e)

    const int arow_l = lrow + ((sub & 1) << 3);
    const int akoff  = (sub >> 1) << 3;
    const int bn_l   = lrow + ((sub >> 1) << 3);
    const int bkoff  = (sub & 1) << 3;
    const int vtrow  = lrow + ((sub & 1) << 3);
    const int vncol  = (sub >> 1) << 3;

    // ---- stage Q ----
    {
        const int qr  = tid >> 1;
        const int qc  = (tid & 1) * 32;
        const __half* src = &Q[(rowbase + q0 + qr) * DIM + colbase + qc];
        const uint32_t dst = smu + (uint32_t)(qr * QSTR + qc) * 2u;
#pragma unroll
        for (int i = 0; i < 4; i++)
            CP_ASYNC16(dst + i * 16, src + i * 8);
    }

    // K/V loader: 128 rows x 64 halves each
    const int kr = tid >> 2;                 // 0..63
    const int kc = (tid & 3) * 16;
    auto load_kv = [&](int s, int t0) {
        const uint32_t kb = smu + (uint32_t)(SK_OFF + s * KVBUF) * 2u;
        const uint32_t vb = smu + (uint32_t)(SV_OFF + s * KVBUF) * 2u;
#pragma unroll
        for (int i = 0; i < 2; i++) {
            const int r = kr + i * 64;
            const uint32_t off = (uint32_t)(r * QSTR + kc) * 2u;
            const __half* ksrc = &K[(rowbase + t0 + r) * DIM + colbase + kc];
            const __half* vsrc = &V[(rowbase + t0 + r) * DIM + colbase + kc];
            CP_ASYNC16(kb + off,      ksrc);
            CP_ASYNC16(kb + off + 16, ksrc + 8);
            CP_ASYNC16(vb + off,      vsrc);
            CP_ASYNC16(vb + off + 16, vsrc + 8);
        }
        CP_COMMIT();
    };

    load_kv(0, 0);   // commits Q loads too

    float m0 = -CUDART_INF_F, m1 = -CUDART_INF_F;
    float l0 = 0.f, l1 = 0.f;
    float accO[8][4];
#pragma unroll
    for (int ni = 0; ni < 8; ni++)
#pragma unroll
        for (int c = 0; c < 4; c++) accO[ni][c] = 0.f;

    for (int t0 = 0; t0 < SEQ; t0 += 128) {
        const int cur = (t0 >> 7) & 1;
        CP_WAIT(0);
        __syncthreads();
        if (t0 + 128 < SEQ) load_kv(cur ^ 1, t0 + 128);

#pragma unroll
        for (int hf = 0; hf < 2; hf++) {
            const uint32_t kBase = smu +
                (uint32_t)(SK_OFF + cur * KVBUF + hf * 64 * QSTR) * 2u;
            const uint32_t vBase = smu +
                (uint32_t)(SV_OFF + cur * KVBUF + hf * 64 * QSTR) * 2u;

            // ---- S = Q @ K^T (fp32 accum) ----
            float sfr[8][4];
#pragma unroll
            for (int ni = 0; ni < 8; ni++)
#pragma unroll
                for (int c = 0; c < 4; c++) sfr[ni][c] = 0.f;

#pragma unroll
            for (int ks = 0; ks < 4; ks++) {
                uint32_t af[4];
                {
                    const uint32_t a = smu +
                        (uint32_t)((wm + arow_l) * QSTR + ks * 16 + akoff) * 2u;
                    LDSM_X4(af[0], af[1], af[2], af[3], a);
                }
#pragma unroll
                for (int pi = 0; pi < 4; pi++) {
                    const uint32_t a = kBase +
                        (uint32_t)((bn_l + pi * 16) * QSTR + ks * 16 + bkoff) * 2u;
                    uint32_t r0, r1, r2, r3;
                    LDSM_X4(r0, r1, r2, r3, a);
                    uint32_t bf0[2] = { r0, r1 }, bf1[2] = { r2, r3 };
                    mma_f16(sfr[2 * pi],     af, bf0);
                    mma_f16(sfr[2 * pi + 1], af, bf1);
                }
            }

            // ---- online softmax (exp in fp16x2, stats in fp32) ----
            float mt0 = sfr[0][0], mt1 = sfr[0][2];
#pragma unroll
            for (int ni = 0; ni < 8; ni++) {
                mt0 = fmaxf(mt0, fmaxf(sfr[ni][0], sfr[ni][1]));
                mt1 = fmaxf(mt1, fmaxf(sfr[ni][2], sfr[ni][3]));
            }
            mt0 = fmaxf(mt0, __shfl_xor_sync(0xffffffffu, mt0, 1));
            mt0 = fmaxf(mt0, __shfl_xor_sync(0xffffffffu, mt0, 2));
            mt1 = fmaxf(mt1, __shfl_xor_sync(0xffffffffu, mt1, 1));
            mt1 = fmaxf(mt1, __shfl_xor_sync(0xffffffffu, mt1, 2));
            mt0 *= cscale;
            mt1 *= cscale;

            const float mn0 = fmaxf(m0, mt0);
            const float mn1 = fmaxf(m1, mt1);
            const float al0 = ex2f(m0 - mn0);
            const float al1 = ex2f(m1 - mn1);
            m0 = mn0; m1 = mn1;

            float lt0 = 0.f, lt1 = 0.f;
#pragma unroll
            for (int ni = 0; ni < 8; ni++) {
                const float a0 = fmaf(sfr[ni][0], cscale, -mn0);
                const float a1 = fmaf(sfr[ni][1], cscale, -mn0);
                const float a2 = fmaf(sfr[ni][2], cscale, -mn1);
                const float a3 = fmaf(sfr[ni][3], cscale, -mn1);
                uint32_t h01, h23, p01, p23;
                // d = {hi = first src, lo = second src}
                asm("cvt.rn.f16x2.f32 %0, %1, %2;" : "=r"(h01) : "f"(a1), "f"(a0));
                asm("cvt.rn.f16x2.f32 %0, %1, %2;" : "=r"(h23) : "f"(a3), "f"(a2));
                asm("ex2.approx.f16x2 %0, %1;" : "=r"(p01) : "r"(h01));
                asm("ex2.approx.f16x2 %0, %1;" : "=r"(p23) : "r"(h23));
                *reinterpret_cast<uint32_t*>(
                    &sP[(wm + g) * QSTR + ni * 8 + 2 * t]) = p01;
                *reinterpret_cast<uint32_t*>(
                    &sP[(wm + g + 8) * QSTR + ni * 8 + 2 * t]) = p23;
                const float2 f01 = __half22float2(
                    *reinterpret_cast<__half2*>(&p01));
                const float2 f23 = __half22float2(
                    *reinterpret_cast<__half2*>(&p23));
                lt0 += f01.x + f01.y;
                lt1 += f23.x + f23.y;
            }
            lt0 += __shfl_xor_sync(0xffffffffu, lt0, 1);
            lt0 += __shfl_xor_sync(0xffffffffu, lt0, 2);
            lt1 += __shfl_xor_sync(0xffffffffu, lt1, 1);
            lt1 += __shfl_xor_sync(0xffffffffu, lt1, 2);
            l0 = l0 * al0 + lt0;
            l1 = l1 * al1 + lt1;

#pragma unroll
            for (int ni = 0; ni < 8; ni++) {
                accO[ni][0] *= al0; accO[ni][1] *= al0;
                accO[ni][2] *= al1; accO[ni][3] *= al1;
            }
            __syncwarp();   // sP rows are warp-private

            // ---- O += P @ V ----
#pragma unroll
            for (int ks = 0; ks < 4; ks++) {
                uint32_t pf[4];
                {
                    const uint32_t a = smu +
                        (uint32_t)(SP_OFF * 2) +
                        (uint32_t)((wm + arow_l) * QSTR + ks * 16 + akoff) * 2u;
                    LDSM_X4(pf[0], pf[1], pf[2], pf[3], a);
                }
#pragma unroll
                for (int pi = 0; pi < 4; pi++) {
                    const uint32_t a = vBase +
                        (uint32_t)((ks * 16 + vtrow) * QSTR + pi * 16 + vncol) * 2u;
                    uint32_t r0, r1, r2, r3;
                    LDSM_X4_T(r0, r1, r2, r3, a);
                    uint32_t bf0[2] = { r0, r1 }, bf1[2] = { r2, r3 };
                    mma_f16(accO[2 * pi],     pf, bf0);
                    mma_f16(accO[2 * pi + 1], pf, bf1);
                }
            }
            __syncwarp();   // done reading sP before next sub-tile overwrites it
        }
    }

    const float inv0 = 1.f / l0;
    const float inv1 = 1.f / l1;
#pragma unroll
    for (int ni = 0; ni < 8; ni++) {
        const int col = colbase + ni * 8 + 2 * t;
        *reinterpret_cast<__half2*>(&O[(rowbase + q0 + wm + g) * DIM + col]) =
            __floats2half2_rn(accO[ni][0] * inv0, accO[ni][1] * inv0);
        *reinterpret_cast<__half2*>(&O[(rowbase + q0 + wm + g + 8) * DIM + col]) =
            __floats2half2_rn(accO[ni][2] * inv1, accO[ni][3] * inv1);
    }
}

// ===========================================================================
extern "C" void kernel_launch(void* const* d_in, const int* in_sizes, int n_in,
                              void* d_out, int out_size)
{
    const float* x  = (const float*)d_in[0];
    const float* Wq = (const float*)d_in[1];
    const float* bq = (const float*)d_in[2];
    const float* Wk = (const float*)d_in[3];
    const float* bk = (const float*)d_in[4];
    const float* Wv = (const float*)d_in[5];
    const float* bv = (const float*)d_in[6];
    const float* Wo = (const float*)d_in[7];
    const float* bo = (const float*)d_in[8];
    float* out = (float*)d_out;

    __half *xh, *wh, *qh, *kh, *vh, *ctxh;
    cudaGetSymbolAddress((void**)&xh,   g_xh);
    cudaGetSymbolAddress((void**)&wh,   g_wh);
    cudaGetSymbolAddress((void**)&qh,   g_qh);
    cudaGetSymbolAddress((void**)&kh,   g_kh);
    cudaGetSymbolAddress((void**)&vh,   g_vh);
    cudaGetSymbolAddress((void**)&ctxh, g_ctxh);
    __half* wqh = wh;
    __half* wkh = wh + DIM * DIM;
    __half* wvh = wh + 2 * DIM * DIM;
    __half* woh = wh + 3 * DIM * DIM;

    // 1) fused prep: x and all W's -> fp16, one launch (z-split)
    {
        dim3 pg(PREP_CHUNK / 256, 1, 5);
        f2h_multi_kernel<<<pg, 256>>>(
            (const float2*)x, (const float2*)Wq, (const float2*)Wk,
            (const float2*)Wv, (const float2*)Wo,
            (__half2*)xh, (__half2*)wh);
    }

    cudaFuncSetAttribute(gemm_h_kernel,
                         cudaFuncAttributeMaxDynamicSharedMemorySize,
                         GEMM_SMEM_BYTES);

    // 2) fused QKV projections (fp16 outputs)
    {
        dim3 gg(DIM / 128, NTOK / 128, 3);
        gemm_h_kernel<<<gg, 256, GEMM_SMEM_BYTES>>>(
            xh, wqh, wkh, wvh, bq, bk, bv, qh, kh, vh, 1);
    }

    // 3) attention (128-key staging, fp16x2 softmax)
    cudaFuncSetAttribute(attn_h_kernel,
                         cudaFuncAttributeMaxDynamicSharedMemorySize,
                         ATTN_SMEM_BYTES);
    attn_h_kernel<<<dim3(SEQ / 128, HEADS, BATCH), 256, ATTN_SMEM_BYTES>>>(
        qh, kh, vh, ctxh);

    // 4) output projection (fp32 output)
    {
        dim3 gg(DIM / 128, NTOK / 128, 1);
        gemm_h_kernel<<<gg, 256, GEMM_SMEM_BYTES>>>(
            ctxh, woh, woh, woh, bo, bo, bo, out, out, out, 0);
    }
}

// round 14
// speedup vs baseline: 1.0069x; 1.0069x over previous
#include <cuda_runtime.h>
#include <cuda_fp16.h>
#include <math_constants.h>
#include <cstdint>

#define NTOK 4096      // B*S
#define DIM  1024
#define HEADS 16
#define HDIM 64
#define SEQ  2048
#define BATCH 2

// Scratch (allocation-free requirement -> __device__ globals), all fp16
__device__ __half g_xh[NTOK * DIM];
__device__ __half g_wh[4 * DIM * DIM];    // fp16 Wq,Wk,Wv,Wo (natural [K][N])
__device__ __half g_qh[NTOK * DIM];
__device__ __half g_kh[NTOK * DIM];
__device__ __half g_vh[NTOK * DIM];
__device__ __half g_ctxh[NTOK * DIM];

// ===========================================================================
// Helpers
// ===========================================================================
__device__ __forceinline__ float ex2f(float x) {
    float y;
    asm("ex2.approx.ftz.f32 %0, %1;" : "=f"(y) : "f"(x));
    return y;
}

#define CP_ASYNC16(smem_addr, gmem_ptr) \
    asm volatile("cp.async.cg.shared.global [%0], [%1], 16;" \
                 :: "r"((uint32_t)(smem_addr)), "l"(gmem_ptr) : "memory")
#define CP_COMMIT() asm volatile("cp.async.commit_group;" ::: "memory")
#define CP_WAIT(n)  asm volatile("cp.async.wait_group %0;" :: "n"(n) : "memory")

__device__ __forceinline__ uint32_t smem_u32(const void* p) {
    uint32_t a;
    asm("{ .reg .u64 t; cvta.to.shared.u64 t, %1; cvt.u32.u64 %0, t; }"
        : "=r"(a) : "l"(p));
    return a;
}

#define LDSM_X4(r0, r1, r2, r3, addr) \
    asm volatile("ldmatrix.sync.aligned.m8n8.x4.shared.b16 {%0,%1,%2,%3}, [%4];" \
                 : "=r"(r0), "=r"(r1), "=r"(r2), "=r"(r3) : "r"(addr))

#define LDSM_X4_T(r0, r1, r2, r3, addr) \
    asm volatile("ldmatrix.sync.aligned.m8n8.x4.trans.shared.b16 {%0,%1,%2,%3}, [%4];" \
                 : "=r"(r0), "=r"(r1), "=r"(r2), "=r"(r3) : "r"(addr))

// mma m16n8k16 fp16 in, fp32 accum
__device__ __forceinline__ void mma_f16(
    float* d, const uint32_t* a, const uint32_t* b)
{
    asm volatile(
        "mma.sync.aligned.m16n8k16.row.col.f32.f16.f16.f32 "
        "{%0,%1,%2,%3}, {%4,%5,%6,%7}, {%8,%9}, {%0,%1,%2,%3};"
        : "+f"(d[0]), "+f"(d[1]), "+f"(d[2]), "+f"(d[3])
        : "r"(a[0]), "r"(a[1]), "r"(a[2]), "r"(a[3]),
          "r"(b[0]), "r"(b[1]));
}

// ===========================================================================
// fp16 GEMM (exact R9/R12 version — unchanged).
// ===========================================================================
#define GDIM 1024
#define BKH 64
#define ASTRH 72
#define BSTRH 136
#define A_STH (128 * ASTRH)          // 9216 halves
#define B_STH (BKH * BSTRH)          // 8704 halves
#define STH   (A_STH + B_STH)        // 17920 halves per stage
#define NSTG  3
#define GEMM_SMEM_BYTES (NSTG * STH * 2)   // 107520 B

__global__ void __launch_bounds__(256, 2) gemm_h_kernel(
    const __half* __restrict__ A,
    const __half* __restrict__ W0, const __half* __restrict__ W1,
    const __half* __restrict__ W2,
    const float* __restrict__ b0p, const float* __restrict__ b1p,
    const float* __restrict__ b2p,
    void* __restrict__ C0, void* __restrict__ C1, void* __restrict__ C2,
    int out_half)
{
    extern __shared__ __align__(16) __half smh[];

    const int z = blockIdx.z;
    const __half* W    = (z == 0) ? W0 : (z == 1) ? W1 : W2;
    const float*  bias = (z == 0) ? b0p : (z == 1) ? b1p : b2p;
    void*         Cv   = (z == 0) ? C0 : (z == 1) ? C1 : C2;

    const int tid  = threadIdx.x;
    const int wid  = tid >> 5;
    const int lane = tid & 31;
    const int g    = lane >> 2;
    const int t    = lane & 3;
    const int lrow = lane & 7;
    const int sub  = lane >> 3;      // 0..3
    const int wm   = wid >> 1;       // 0..3
    const int wn   = wid & 1;        // 0..1

    const int brow = blockIdx.y * 128;
    const int bcol = blockIdx.x * 128;

    const uint32_t smu = smem_u32(smh);

    const int arow_l = wm * 32 + lrow + ((sub & 1) << 3);
    const int akoff  = (sub >> 1) << 3;
    const int btrow  = lrow + ((sub & 1) << 3);
    const int bncol  = (sub >> 1) << 3;

    const int alr = tid >> 3;
    const int alc = (tid & 7) * 8;
    const __half* Asrc = A + (size_t)(brow + alr) * GDIM + alc;
    const int blr = tid >> 4;
    const int blc = (tid & 15) * 8;

    auto load_stage = [&](int s, int kt) {
        const int k0 = kt * BKH;
        const uint32_t abase = smu + (uint32_t)(s * STH) * 2u;
        const uint32_t bbase = abase + (uint32_t)A_STH * 2u;
#pragma unroll
        for (int i = 0; i < 4; i++) {
            const int ra = alr + i * 32;
            CP_ASYNC16(abase + (uint32_t)(ra * ASTRH + alc) * 2u,
                       Asrc + (size_t)(i * 32) * GDIM + k0);
            const int rb = blr + i * 16;
            CP_ASYNC16(bbase + (uint32_t)(rb * BSTRH + blc) * 2u,
                       W + (size_t)(k0 + rb) * GDIM + bcol + blc);
        }
        CP_COMMIT();
    };

    float acc[2][8][4];
#pragma unroll
    for (int mi = 0; mi < 2; mi++)
#pragma unroll
        for (int ni = 0; ni < 8; ni++)
#pragma unroll
            for (int c = 0; c < 4; c++) acc[mi][ni][c] = 0.f;

    load_stage(0, 0);
    load_stage(1, 1);

    const int NKT = GDIM / BKH;   // 16
    for (int kt = 0; kt < NKT; ++kt) {
        const int cur = kt % NSTG;
        CP_WAIT(1);
        __syncthreads();

        const uint32_t aBase = smu + (uint32_t)(cur * STH) * 2u;
        const uint32_t bBase = aBase + (uint32_t)A_STH * 2u;

#pragma unroll
        for (int ks = 0; ks < 4; ks++) {
            uint32_t af[2][4];
#pragma unroll
            for (int mi = 0; mi < 2; mi++) {
                const uint32_t a = aBase +
                    (uint32_t)((arow_l + mi * 16) * ASTRH + ks * 16 + akoff) * 2u;
                LDSM_X4(af[mi][0], af[mi][1], af[mi][2], af[mi][3], a);
            }
            uint32_t bf[8][2];
#pragma unroll
            for (int pi = 0; pi < 4; pi++) {
                const uint32_t a = bBase +
                    (uint32_t)((ks * 16 + btrow) * BSTRH +
                               wn * 64 + pi * 16 + bncol) * 2u;
                uint32_t r0, r1, r2, r3;
                LDSM_X4_T(r0, r1, r2, r3, a);
                bf[2 * pi][0] = r0; bf[2 * pi][1] = r1;
                bf[2 * pi + 1][0] = r2; bf[2 * pi + 1][1] = r3;
            }
#pragma unroll
            for (int mi = 0; mi < 2; mi++)
#pragma unroll
                for (int ni = 0; ni < 8; ni++)
                    mma_f16(acc[mi][ni], af[mi], bf[ni]);
        }

        if (kt + 2 < NKT) load_stage((kt + 2) % NSTG, kt + 2);
    }

    // Epilogue
#pragma unroll
    for (int ni = 0; ni < 8; ni++) {
        const int col = bcol + wn * 64 + ni * 8 + t * 2;
        const float2 bv = *reinterpret_cast<const float2*>(&bias[col]);
#pragma unroll
        for (int mi = 0; mi < 2; mi++) {
            const int r0 = brow + wm * 32 + mi * 16 + g;
            float2 v0, v1;
            v0.x = acc[mi][ni][0] + bv.x;
            v0.y = acc[mi][ni][1] + bv.y;
            v1.x = acc[mi][ni][2] + bv.x;
            v1.y = acc[mi][ni][3] + bv.y;
            if (out_half) {
                __half* C = (__half*)Cv;
                *reinterpret_cast<__half2*>(&C[(size_t)r0 * GDIM + col]) =
                    __floats2half2_rn(v0.x, v0.y);
                *reinterpret_cast<__half2*>(&C[(size_t)(r0 + 8) * GDIM + col]) =
                    __floats2half2_rn(v1.x, v1.y);
            } else {
                float* C = (float*)Cv;
                *reinterpret_cast<float2*>(&C[(size_t)r0 * GDIM + col])       = v0;
                *reinterpret_cast<float2*>(&C[(size_t)(r0 + 8) * GDIM + col]) = v1;
            }
        }
    }
}

// ===========================================================================
// Balanced prep: grid z = 8.  z<4 -> W[z]; z>=4 -> quarter (z-4) of x.
// Every thread converts exactly one half2 (straight-line body, no loop).
// ===========================================================================
#define PREP_CHUNK (DIM * DIM / 2)   // 524288 half2 per W (= per x quarter)

__global__ void f2h_multi_kernel(
    const float2* __restrict__ x,
    const float2* __restrict__ Wq, const float2* __restrict__ Wk,
    const float2* __restrict__ Wv, const float2* __restrict__ Wo,
    __half2* __restrict__ xh, __half2* __restrict__ wh)
{
    const int z = blockIdx.z;
    const int i = blockIdx.x * blockDim.x + threadIdx.x;
    if (z < 4) {
        const float2* src = (z == 0) ? Wq : (z == 1) ? Wk : (z == 2) ? Wv : Wo;
        float2 v = src[i];
        wh[(size_t)z * PREP_CHUNK + i] = __floats2half2_rn(v.x, v.y);
    } else {
        const size_t idx = (size_t)(z - 4) * PREP_CHUNK + i;
        float2 v = x[idx];
        xh[idx] = __floats2half2_rn(v.x, v.y);
    }
}

// ===========================================================================
// fp16 flash attention (exact R12 version: 128-key staging, two 64-key
// sub-tiles, fp32 ex2 softmax).
// ===========================================================================
#define QSTR 72
#define SP_OFF   (128 * QSTR)
#define SK_OFF   (2 * 128 * QSTR)
#define KVBUF    (128 * QSTR)                 // one 128-key buffer
#define SV_OFF   (SK_OFF + 2 * KVBUF)
#define ATTN_SMEM_BYTES ((2 * 128 * QSTR + 4 * KVBUF) * 2)   // 110592 B

__global__ void __launch_bounds__(256, 2) attn_h_kernel(
    const __half* __restrict__ Q, const __half* __restrict__ K,
    const __half* __restrict__ V, __half* __restrict__ O)
{
    extern __shared__ __align__(16) __half smh[];
    const uint32_t smu = smem_u32(smh);
    __half* sP = smh + SP_OFF;

    const int tid  = threadIdx.x;
    const int wid  = tid >> 5;
    const int lane = tid & 31;
    const int g    = lane >> 2;
    const int t    = lane & 3;
    const int lrow = lane & 7;
    const int sub  = lane >> 3;
    const int wm   = wid * 16;

    const int q0 = blockIdx.x * 128;
    const int h  = blockIdx.y;
    const int b  = blockIdx.z;
    const size_t rowbase = (size_t)b * SEQ;
    const int colbase = h * HDIM;

    const float cscale = 0.125f * 1.4426950408889634f;  // 1/sqrt(64)*log2(e)

    const int arow_l = lrow + ((sub & 1) << 3);
    const int akoff  = (sub >> 1) << 3;
    const int bn_l   = lrow + ((sub >> 1) << 3);
    const int bkoff  = (sub & 1) << 3;
    const int vtrow  = lrow + ((sub & 1) << 3);
    const int vncol  = (sub >> 1) << 3;

    // ---- stage Q ----
    {
        const int qr  = tid >> 1;
        const int qc  = (tid & 1) * 32;
        const __half* src = &Q[(rowbase + q0 + qr) * DIM + colbase + qc];
        const uint32_t dst = smu + (uint32_t)(qr * QSTR + qc) * 2u;
#pragma unroll
        for (int i = 0; i < 4; i++)
            CP_ASYNC16(dst + i * 16, src + i * 8);
    }

    // K/V loader: 128 rows x 64 halves each; per thread rows kr, kr+64,
    // 2 chunks per row per operand.
    const int kr = tid >> 2;                 // 0..63
    const int kc = (tid & 3) * 16;
    auto load_kv = [&](int s, int t0) {
        const uint32_t kb = smu + (uint32_t)(SK_OFF + s * KVBUF) * 2u;
        const uint32_t vb = smu + (uint32_t)(SV_OFF + s * KVBUF) * 2u;
#pragma unroll
        for (int i = 0; i < 2; i++) {
            const int r = kr + i * 64;
            const uint32_t off = (uint32_t)(r * QSTR + kc) * 2u;
            const __half* ksrc = &K[(rowbase + t0 + r) * DIM + colbase + kc];
            const __half* vsrc = &V[(rowbase + t0 + r) * DIM + colbase + kc];
            CP_ASYNC16(kb + off,      ksrc);
            CP_ASYNC16(kb + off + 16, ksrc + 8);
            CP_ASYNC16(vb + off,      vsrc);
            CP_ASYNC16(vb + off + 16, vsrc + 8);
        }
        CP_COMMIT();
    };

    load_kv(0, 0);   // commits Q loads too

    float m0 = -CUDART_INF_F, m1 = -CUDART_INF_F;
    float l0 = 0.f, l1 = 0.f;
    float accO[8][4];
#pragma unroll
    for (int ni = 0; ni < 8; ni++)
#pragma unroll
        for (int c = 0; c < 4; c++) accO[ni][c] = 0.f;

    for (int t0 = 0; t0 < SEQ; t0 += 128) {
        const int cur = (t0 >> 7) & 1;
        CP_WAIT(0);
        __syncthreads();
        if (t0 + 128 < SEQ) load_kv(cur ^ 1, t0 + 128);

#pragma unroll
        for (int hf = 0; hf < 2; hf++) {
            const uint32_t kBase = smu +
                (uint32_t)(SK_OFF + cur * KVBUF + hf * 64 * QSTR) * 2u;
            const uint32_t vBase = smu +
                (uint32_t)(SV_OFF + cur * KVBUF + hf * 64 * QSTR) * 2u;

            // ---- S = Q @ K^T (fp32 accum) ----
            float sfr[8][4];
#pragma unroll
            for (int ni = 0; ni < 8; ni++)
#pragma unroll
                for (int c = 0; c < 4; c++) sfr[ni][c] = 0.f;

#pragma unroll
            for (int ks = 0; ks < 4; ks++) {
                uint32_t af[4];
                {
                    const uint32_t a = smu +
                        (uint32_t)((wm + arow_l) * QSTR + ks * 16 + akoff) * 2u;
                    LDSM_X4(af[0], af[1], af[2], af[3], a);
                }
#pragma unroll
                for (int pi = 0; pi < 4; pi++) {
                    const uint32_t a = kBase +
                        (uint32_t)((bn_l + pi * 16) * QSTR + ks * 16 + bkoff) * 2u;
                    uint32_t r0, r1, r2, r3;
                    LDSM_X4(r0, r1, r2, r3, a);
                    uint32_t bf0[2] = { r0, r1 }, bf1[2] = { r2, r3 };
                    mma_f16(sfr[2 * pi],     af, bf0);
                    mma_f16(sfr[2 * pi + 1], af, bf1);
                }
            }

            // ---- online softmax (fp32 ex2, R12-exact) ----
            float mt0 = sfr[0][0], mt1 = sfr[0][2];
#pragma unroll
            for (int ni = 0; ni < 8; ni++) {
                mt0 = fmaxf(mt0, fmaxf(sfr[ni][0], sfr[ni][1]));
                mt1 = fmaxf(mt1, fmaxf(sfr[ni][2], sfr[ni][3]));
            }
            mt0 = fmaxf(mt0, __shfl_xor_sync(0xffffffffu, mt0, 1));
            mt0 = fmaxf(mt0, __shfl_xor_sync(0xffffffffu, mt0, 2));
            mt1 = fmaxf(mt1, __shfl_xor_sync(0xffffffffu, mt1, 1));
            mt1 = fmaxf(mt1, __shfl_xor_sync(0xffffffffu, mt1, 2));
            mt0 *= cscale;
            mt1 *= cscale;

            const float mn0 = fmaxf(m0, mt0);
            const float mn1 = fmaxf(m1, mt1);
            const float al0 = ex2f(m0 - mn0);
            const float al1 = ex2f(m1 - mn1);
            m0 = mn0; m1 = mn1;

            float lt0 = 0.f, lt1 = 0.f;
#pragma unroll
            for (int ni = 0; ni < 8; ni++) {
                float p0 = ex2f(sfr[ni][0] * cscale - mn0);
                float p1 = ex2f(sfr[ni][1] * cscale - mn0);
                float p2 = ex2f(sfr[ni][2] * cscale - mn1);
                float p3 = ex2f(sfr[ni][3] * cscale - mn1);
                lt0 += p0 + p1;
                lt1 += p2 + p3;
                *reinterpret_cast<__half2*>(&sP[(wm + g) * QSTR + ni * 8 + 2 * t]) =
                    __floats2half2_rn(p0, p1);
                *reinterpret_cast<__half2*>(&sP[(wm + g + 8) * QSTR + ni * 8 + 2 * t]) =
                    __floats2half2_rn(p2, p3);
            }
            lt0 += __shfl_xor_sync(0xffffffffu, lt0, 1);
            lt0 += __shfl_xor_sync(0xffffffffu, lt0, 2);
            lt1 += __shfl_xor_sync(0xffffffffu, lt1, 1);
            lt1 += __shfl_xor_sync(0xffffffffu, lt1, 2);
            l0 = l0 * al0 + lt0;
            l1 = l1 * al1 + lt1;

#pragma unroll
            for (int ni = 0; ni < 8; ni++) {
                accO[ni][0] *= al0; accO[ni][1] *= al0;
                accO[ni][2] *= al1; accO[ni][3] *= al1;
            }
            __syncwarp();   // sP rows are warp-private

            // ---- O += P @ V ----
#pragma unroll
            for (int ks = 0; ks < 4; ks++) {
                uint32_t pf[4];
                {
                    const uint32_t a = smu +
                        (uint32_t)(SP_OFF * 2) +
                        (uint32_t)((wm + arow_l) * QSTR + ks * 16 + akoff) * 2u;
                    LDSM_X4(pf[0], pf[1], pf[2], pf[3], a);
                }
#pragma unroll
                for (int pi = 0; pi < 4; pi++) {
                    const uint32_t a = vBase +
                        (uint32_t)((ks * 16 + vtrow) * QSTR + pi * 16 + vncol) * 2u;
                    uint32_t r0, r1, r2, r3;
                    LDSM_X4_T(r0, r1, r2, r3, a);
                    uint32_t bf0[2] = { r0, r1 }, bf1[2] = { r2, r3 };
                    mma_f16(accO[2 * pi],     pf, bf0);
                    mma_f16(accO[2 * pi + 1], pf, bf1);
                }
            }
            __syncwarp();   // done reading sP before next sub-tile overwrites it
        }
    }

    const float inv0 = 1.f / l0;
    const float inv1 = 1.f / l1;
#pragma unroll
    for (int ni = 0; ni < 8; ni++) {
        const int col = colbase + ni * 8 + 2 * t;
        *reinterpret_cast<__half2*>(&O[(rowbase + q0 + wm + g) * DIM + col]) =
            __floats2half2_rn(accO[ni][0] * inv0, accO[ni][1] * inv0);
        *reinterpret_cast<__half2*>(&O[(rowbase + q0 + wm + g + 8) * DIM + col]) =
            __floats2half2_rn(accO[ni][2] * inv1, accO[ni][3] * inv1);
    }
}

// ===========================================================================
extern "C" void kernel_launch(void* const* d_in, const int* in_sizes, int n_in,
                              void* d_out, int out_size)
{
    const float* x  = (const float*)d_in[0];
    const float* Wq = (const float*)d_in[1];
    const float* bq = (const float*)d_in[2];
    const float* Wk = (const float*)d_in[3];
    const float* bk = (const float*)d_in[4];
    const float* Wv = (const float*)d_in[5];
    const float* bv = (const float*)d_in[6];
    const float* Wo = (const float*)d_in[7];
    const float* bo = (const float*)d_in[8];
    float* out = (float*)d_out;

    __half *xh, *wh, *qh, *kh, *vh, *ctxh;
    cudaGetSymbolAddress((void**)&xh,   g_xh);
    cudaGetSymbolAddress((void**)&wh,   g_wh);
    cudaGetSymbolAddress((void**)&qh,   g_qh);
    cudaGetSymbolAddress((void**)&kh,   g_kh);
    cudaGetSymbolAddress((void**)&vh,   g_vh);
    cudaGetSymbolAddress((void**)&ctxh, g_ctxh);
    __half* wqh = wh;
    __half* wkh = wh + DIM * DIM;
    __half* wvh = wh + 2 * DIM * DIM;
    __half* woh = wh + 3 * DIM * DIM;

    // 1) balanced prep: x (4 quarters) + 4 W's, one launch, uniform blocks
    {
        dim3 pg(PREP_CHUNK / 256, 1, 8);
        f2h_multi_kernel<<<pg, 256>>>(
            (const float2*)x, (const float2*)Wq, (const float2*)Wk,
            (const float2*)Wv, (const float2*)Wo,
            (__half2*)xh, (__half2*)wh);
    }

    cudaFuncSetAttribute(gemm_h_kernel,
                         cudaFuncAttributeMaxDynamicSharedMemorySize,
                         GEMM_SMEM_BYTES);

    // 2) fused QKV projections (fp16 outputs)
    {
        dim3 gg(DIM / 128, NTOK / 128, 3);
        gemm_h_kernel<<<gg, 256, GEMM_SMEM_BYTES>>>(
            xh, wqh, wkh, wvh, bq, bk, bv, qh, kh, vh, 1);
    }

    // 3) attention (128-key staging, fp32 ex2 softmax — R12 exact)
    cudaFuncSetAttribute(attn_h_kernel,
                         cudaFuncAttributeMaxDynamicSharedMemorySize,
                         ATTN_SMEM_BYTES);
    attn_h_kernel<<<dim3(SEQ / 128, HEADS, BATCH), 256, ATTN_SMEM_BYTES>>>(
        qh, kh, vh, ctxh);

    // 4) output projection (fp32 output)
    {
        dim3 gg(DIM / 128, NTOK / 128, 1);
        gemm_h_kernel<<<gg, 256, GEMM_SMEM_BYTES>>>(
            ctxh, woh, woh, woh, bo, bo, bo, out, out, out, 0);
    }
}

// round 15
// speedup vs baseline: 1.0201x; 1.0131x over previous
#include <cuda_runtime.h>
#include <cuda_fp16.h>
#include <math_constants.h>
#include <cstdint>

#define NTOK 4096      // B*S
#define DIM  1024
#define HEADS 16
#define HDIM 64
#define SEQ  2048
#define BATCH 2

// Scratch (allocation-free requirement -> __device__ globals), all fp16
__device__ __half g_xh[NTOK * DIM];
__device__ __half g_wh[4 * DIM * DIM];    // fp16 Wq,Wk,Wv,Wo (natural [K][N])
__device__ __half g_qh[NTOK * DIM];
__device__ __half g_kh[NTOK * DIM];
__device__ __half g_vh[NTOK * DIM];
__device__ __half g_ctxh[NTOK * DIM];

// ===========================================================================
// Helpers
// ===========================================================================
__device__ __forceinline__ float ex2f(float x) {
    float y;
    asm("ex2.approx.ftz.f32 %0, %1;" : "=f"(y) : "f"(x));
    return y;
}

#define CP_ASYNC16(smem_addr, gmem_ptr) \
    asm volatile("cp.async.cg.shared.global [%0], [%1], 16;" \
                 :: "r"((uint32_t)(smem_addr)), "l"(gmem_ptr) : "memory")
#define CP_COMMIT() asm volatile("cp.async.commit_group;" ::: "memory")
#define CP_WAIT(n)  asm volatile("cp.async.wait_group %0;" :: "n"(n) : "memory")

__device__ __forceinline__ uint32_t smem_u32(const void* p) {
    uint32_t a;
    asm("{ .reg .u64 t; cvta.to.shared.u64 t, %1; cvt.u32.u64 %0, t; }"
        : "=r"(a) : "l"(p));
    return a;
}

#define LDSM_X4(r0, r1, r2, r3, addr) \
    asm volatile("ldmatrix.sync.aligned.m8n8.x4.shared.b16 {%0,%1,%2,%3}, [%4];" \
                 : "=r"(r0), "=r"(r1), "=r"(r2), "=r"(r3) : "r"(addr))

#define LDSM_X4_T(r0, r1, r2, r3, addr) \
    asm volatile("ldmatrix.sync.aligned.m8n8.x4.trans.shared.b16 {%0,%1,%2,%3}, [%4];" \
                 : "=r"(r0), "=r"(r1), "=r"(r2), "=r"(r3) : "r"(addr))

// mma m16n8k16 fp16 in, fp32 accum
__device__ __forceinline__ void mma_f16(
    float* d, const uint32_t* a, const uint32_t* b)
{
    asm volatile(
        "mma.sync.aligned.m16n8k16.row.col.f32.f16.f16.f32 "
        "{%0,%1,%2,%3}, {%4,%5,%6,%7}, {%8,%9}, {%0,%1,%2,%3};"
        : "+f"(d[0]), "+f"(d[1]), "+f"(d[2]), "+f"(d[3])
        : "r"(a[0]), "r"(a[1]), "r"(a[2]), "r"(a[3]),
          "r"(b[0]), "r"(b[1]));
}

// ===========================================================================
// fp16 GEMM:  C[z] = A @ W[z] + bias[z]
//  A:[4096,1024] fp16 row-major;  W:[K][N] fp16 natural layout via
//  ldmatrix.trans.  CTA tile 128x128, BK=64, 256 thr (8 warps of 32x64),
//  3-stage cp.async ring (CP_WAIT(1)), 2 CTAs/SM.  load_stage after the MMA
//  block (measured faster than hoisting at 2 CTAs/SM).
// ===========================================================================
#define GDIM 1024
#define BKH 64
#define ASTRH 72
#define BSTRH 136
#define A_STH (128 * ASTRH)          // 9216 halves
#define B_STH (BKH * BSTRH)          // 8704 halves
#define STH   (A_STH + B_STH)        // 17920 halves per stage
#define NSTG  3
#define GEMM_SMEM_BYTES (NSTG * STH * 2)   // 107520 B

__global__ void __launch_bounds__(256, 2) gemm_h_kernel(
    const __half* __restrict__ A,
    const __half* __restrict__ W0, const __half* __restrict__ W1,
    const __half* __restrict__ W2,
    const float* __restrict__ b0p, const float* __restrict__ b1p,
    const float* __restrict__ b2p,
    void* __restrict__ C0, void* __restrict__ C1, void* __restrict__ C2,
    int out_half)
{
    extern __shared__ __align__(16) __half smh[];

    const int z = blockIdx.z;
    const __half* W    = (z == 0) ? W0 : (z == 1) ? W1 : W2;
    const float*  bias = (z == 0) ? b0p : (z == 1) ? b1p : b2p;
    void*         Cv   = (z == 0) ? C0 : (z == 1) ? C1 : C2;

    const int tid  = threadIdx.x;
    const int wid  = tid >> 5;
    const int lane = tid & 31;
    const int g    = lane >> 2;
    const int t    = lane & 3;
    const int lrow = lane & 7;
    const int sub  = lane >> 3;      // 0..3
    const int wm   = wid >> 1;       // 0..3
    const int wn   = wid & 1;        // 0..1

    const int brow = blockIdx.y * 128;
    const int bcol = blockIdx.x * 128;

    const uint32_t smu = smem_u32(smh);

    const int arow_l = wm * 32 + lrow + ((sub & 1) << 3);
    const int akoff  = (sub >> 1) << 3;
    const int btrow  = lrow + ((sub & 1) << 3);
    const int bncol  = (sub >> 1) << 3;

    const int alr = tid >> 3;
    const int alc = (tid & 7) * 8;
    const __half* Asrc = A + (size_t)(brow + alr) * GDIM + alc;
    const int blr = tid >> 4;
    const int blc = (tid & 15) * 8;

    auto load_stage = [&](int s, int kt) {
        const int k0 = kt * BKH;
        const uint32_t abase = smu + (uint32_t)(s * STH) * 2u;
        const uint32_t bbase = abase + (uint32_t)A_STH * 2u;
#pragma unroll
        for (int i = 0; i < 4; i++) {
            const int ra = alr + i * 32;
            CP_ASYNC16(abase + (uint32_t)(ra * ASTRH + alc) * 2u,
                       Asrc + (size_t)(i * 32) * GDIM + k0);
            const int rb = blr + i * 16;
            CP_ASYNC16(bbase + (uint32_t)(rb * BSTRH + blc) * 2u,
                       W + (size_t)(k0 + rb) * GDIM + bcol + blc);
        }
        CP_COMMIT();
    };

    float acc[2][8][4];
#pragma unroll
    for (int mi = 0; mi < 2; mi++)
#pragma unroll
        for (int ni = 0; ni < 8; ni++)
#pragma unroll
            for (int c = 0; c < 4; c++) acc[mi][ni][c] = 0.f;

    load_stage(0, 0);
    load_stage(1, 1);

    const int NKT = GDIM / BKH;   // 16
    for (int kt = 0; kt < NKT; ++kt) {
        const int cur = kt % NSTG;
        CP_WAIT(1);
        __syncthreads();

        const uint32_t aBase = smu + (uint32_t)(cur * STH) * 2u;
        const uint32_t bBase = aBase + (uint32_t)A_STH * 2u;

#pragma unroll
        for (int ks = 0; ks < 4; ks++) {
            uint32_t af[2][4];
#pragma unroll
            for (int mi = 0; mi < 2; mi++) {
                const uint32_t a = aBase +
                    (uint32_t)((arow_l + mi * 16) * ASTRH + ks * 16 + akoff) * 2u;
                LDSM_X4(af[mi][0], af[mi][1], af[mi][2], af[mi][3], a);
            }
            uint32_t bf[8][2];
#pragma unroll
            for (int pi = 0; pi < 4; pi++) {
                const uint32_t a = bBase +
                    (uint32_t)((ks * 16 + btrow) * BSTRH +
                               wn * 64 + pi * 16 + bncol) * 2u;
                uint32_t r0, r1, r2, r3;
                LDSM_X4_T(r0, r1, r2, r3, a);
                bf[2 * pi][0] = r0; bf[2 * pi][1] = r1;
                bf[2 * pi + 1][0] = r2; bf[2 * pi + 1][1] = r3;
            }
#pragma unroll
            for (int mi = 0; mi < 2; mi++)
#pragma unroll
                for (int ni = 0; ni < 8; ni++)
                    mma_f16(acc[mi][ni], af[mi], bf[ni]);
        }

        if (kt + 2 < NKT) load_stage((kt + 2) % NSTG, kt + 2);
    }

    // Epilogue
#pragma unroll
    for (int ni = 0; ni < 8; ni++) {
        const int col = bcol + wn * 64 + ni * 8 + t * 2;
        const float2 bv = *reinterpret_cast<const float2*>(&bias[col]);
#pragma unroll
        for (int mi = 0; mi < 2; mi++) {
            const int r0 = brow + wm * 32 + mi * 16 + g;
            float2 v0, v1;
            v0.x = acc[mi][ni][0] + bv.x;
            v0.y = acc[mi][ni][1] + bv.y;
            v1.x = acc[mi][ni][2] + bv.x;
            v1.y = acc[mi][ni][3] + bv.y;
            if (out_half) {
                __half* C = (__half*)Cv;
                *reinterpret_cast<__half2*>(&C[(size_t)r0 * GDIM + col]) =
                    __floats2half2_rn(v0.x, v0.y);
                *reinterpret_cast<__half2*>(&C[(size_t)(r0 + 8) * GDIM + col]) =
                    __floats2half2_rn(v1.x, v1.y);
            } else {
                float* C = (float*)Cv;
                *reinterpret_cast<float2*>(&C[(size_t)r0 * GDIM + col])       = v0;
                *reinterpret_cast<float2*>(&C[(size_t)(r0 + 8) * GDIM + col]) = v1;
            }
        }
    }
}

// ===========================================================================
// Prep (z-split: z<4 -> W[z], z=4 -> x with 4 chunks/thread for MLP=4;
// measured fastest variant).
// ===========================================================================
#define PREP_CHUNK (DIM * DIM / 2)   // 524288 half2 per W

__global__ void f2h_multi_kernel(
    const float2* __restrict__ x,
    const float2* __restrict__ Wq, const float2* __restrict__ Wk,
    const float2* __restrict__ Wv, const float2* __restrict__ Wo,
    __half2* __restrict__ xh, __half2* __restrict__ wh)
{
    const int z = blockIdx.z;
    const int i = blockIdx.x * blockDim.x + threadIdx.x;
    if (z < 4) {
        const float2* src = (z == 0) ? Wq : (z == 1) ? Wk : (z == 2) ? Wv : Wo;
        float2 v = src[i];
        wh[(size_t)z * PREP_CHUNK + i] = __floats2half2_rn(v.x, v.y);
    } else {
#pragma unroll
        for (int j = 0; j < 4; j++) {
            const size_t idx = (size_t)i + (size_t)j * PREP_CHUNK;
            float2 v = x[idx];
            xh[idx] = __floats2half2_rn(v.x, v.y);
        }
    }
}

// ===========================================================================
// fp16 flash attention: 128-key K/V staging (two sequential 64-key
// sub-tiles), double-buffered, ldmatrix(+trans) fragments, fp32 ex2 softmax.
// Smem: sQ 128x72 + sP 128x72 + K 2x128x72 + V 2x128x72 = 110592 B; 2 CTAs/SM.
// ===========================================================================
#define QSTR 72
#define SP_OFF   (128 * QSTR)
#define SK_OFF   (2 * 128 * QSTR)
#define KVBUF    (128 * QSTR)                 // one 128-key buffer
#define SV_OFF   (SK_OFF + 2 * KVBUF)
#define ATTN_SMEM_BYTES ((2 * 128 * QSTR + 4 * KVBUF) * 2)   // 110592 B

__global__ void __launch_bounds__(256, 2) attn_h_kernel(
    const __half* __restrict__ Q, const __half* __restrict__ K,
    const __half* __restrict__ V, __half* __restrict__ O)
{
    extern __shared__ __align__(16) __half smh[];
    const uint32_t smu = smem_u32(smh);
    __half* sP = smh + SP_OFF;

    const int tid  = threadIdx.x;
    const int wid  = tid >> 5;
    const int lane = tid & 31;
    const int g    = lane >> 2;
    const int t    = lane & 3;
    const int lrow = lane & 7;
    const int sub  = lane >> 3;
    const int wm   = wid * 16;

    const int q0 = blockIdx.x * 128;
    const int h  = blockIdx.y;
    const int b  = blockIdx.z;
    const size_t rowbase = (size_t)b * SEQ;
    const int colbase = h * HDIM;

    const float cscale = 0.125f * 1.4426950408889634f;  // 1/sqrt(64)*log2(e)

    const int arow_l = lrow + ((sub & 1) << 3);
    const int akoff  = (sub >> 1) << 3;
    const int bn_l   = lrow + ((sub >> 1) << 3);
    const int bkoff  = (sub & 1) << 3;
    const int vtrow  = lrow + ((sub & 1) << 3);
    const int vncol  = (sub >> 1) << 3;

    // ---- stage Q ----
    {
        const int qr  = tid >> 1;
        const int qc  = (tid & 1) * 32;
        const __half* src = &Q[(rowbase + q0 + qr) * DIM + colbase + qc];
        const uint32_t dst = smu + (uint32_t)(qr * QSTR + qc) * 2u;
#pragma unroll
        for (int i = 0; i < 4; i++)
            CP_ASYNC16(dst + i * 16, src + i * 8);
    }

    // K/V loader: 128 rows x 64 halves each; per thread rows kr, kr+64,
    // 2 chunks per row per operand.
    const int kr = tid >> 2;                 // 0..63
    const int kc = (tid & 3) * 16;
    auto load_kv = [&](int s, int t0) {
        const uint32_t kb = smu + (uint32_t)(SK_OFF + s * KVBUF) * 2u;
        const uint32_t vb = smu + (uint32_t)(SV_OFF + s * KVBUF) * 2u;
#pragma unroll
        for (int i = 0; i < 2; i++) {
            const int r = kr + i * 64;
            const uint32_t off = (uint32_t)(r * QSTR + kc) * 2u;
            const __half* ksrc = &K[(rowbase + t0 + r) * DIM + colbase + kc];
            const __half* vsrc = &V[(rowbase + t0 + r) * DIM + colbase + kc];
            CP_ASYNC16(kb + off,      ksrc);
            CP_ASYNC16(kb + off + 16, ksrc + 8);
            CP_ASYNC16(vb + off,      vsrc);
            CP_ASYNC16(vb + off + 16, vsrc + 8);
        }
        CP_COMMIT();
    };

    load_kv(0, 0);   // commits Q loads too

    float m0 = -CUDART_INF_F, m1 = -CUDART_INF_F;
    float l0 = 0.f, l1 = 0.f;
    float accO[8][4];
#pragma unroll
    for (int ni = 0; ni < 8; ni++)
#pragma unroll
        for (int c = 0; c < 4; c++) accO[ni][c] = 0.f;

    for (int t0 = 0; t0 < SEQ; t0 += 128) {
        const int cur = (t0 >> 7) & 1;
        CP_WAIT(0);
        __syncthreads();
        if (t0 + 128 < SEQ) load_kv(cur ^ 1, t0 + 128);

#pragma unroll
        for (int hf = 0; hf < 2; hf++) {
            const uint32_t kBase = smu +
                (uint32_t)(SK_OFF + cur * KVBUF + hf * 64 * QSTR) * 2u;
            const uint32_t vBase = smu +
                (uint32_t)(SV_OFF + cur * KVBUF + hf * 64 * QSTR) * 2u;

            // ---- S = Q @ K^T (fp32 accum) ----
            float sfr[8][4];
#pragma unroll
            for (int ni = 0; ni < 8; ni++)
#pragma unroll
                for (int c = 0; c < 4; c++) sfr[ni][c] = 0.f;

#pragma unroll
            for (int ks = 0; ks < 4; ks++) {
                uint32_t af[4];
                {
                    const uint32_t a = smu +
                        (uint32_t)((wm + arow_l) * QSTR + ks * 16 + akoff) * 2u;
                    LDSM_X4(af[0], af[1], af[2], af[3], a);
                }
#pragma unroll
                for (int pi = 0; pi < 4; pi++) {
                    const uint32_t a = kBase +
                        (uint32_t)((bn_l + pi * 16) * QSTR + ks * 16 + bkoff) * 2u;
                    uint32_t r0, r1, r2, r3;
                    LDSM_X4(r0, r1, r2, r3, a);
                    uint32_t bf0[2] = { r0, r1 }, bf1[2] = { r2, r3 };
                    mma_f16(sfr[2 * pi],     af, bf0);
                    mma_f16(sfr[2 * pi + 1], af, bf1);
                }
            }

            // ---- online softmax (fp32 ex2) ----
            float mt0 = sfr[0][0], mt1 = sfr[0][2];
#pragma unroll
            for (int ni = 0; ni < 8; ni++) {
                mt0 = fmaxf(mt0, fmaxf(sfr[ni][0], sfr[ni][1]));
                mt1 = fmaxf(mt1, fmaxf(sfr[ni][2], sfr[ni][3]));
            }
            mt0 = fmaxf(mt0, __shfl_xor_sync(0xffffffffu, mt0, 1));
            mt0 = fmaxf(mt0, __shfl_xor_sync(0xffffffffu, mt0, 2));
            mt1 = fmaxf(mt1, __shfl_xor_sync(0xffffffffu, mt1, 1));
            mt1 = fmaxf(mt1, __shfl_xor_sync(0xffffffffu, mt1, 2));
            mt0 *= cscale;
            mt1 *= cscale;

            const float mn0 = fmaxf(m0, mt0);
            const float mn1 = fmaxf(m1, mt1);
            const float al0 = ex2f(m0 - mn0);
            const float al1 = ex2f(m1 - mn1);
            m0 = mn0; m1 = mn1;

            float lt0 = 0.f, lt1 = 0.f;
#pragma unroll
            for (int ni = 0; ni < 8; ni++) {
                float p0 = ex2f(sfr[ni][0] * cscale - mn0);
                float p1 = ex2f(sfr[ni][1] * cscale - mn0);
                float p2 = ex2f(sfr[ni][2] * cscale - mn1);
                float p3 = ex2f(sfr[ni][3] * cscale - mn1);
                lt0 += p0 + p1;
                lt1 += p2 + p3;
                *reinterpret_cast<__half2*>(&sP[(wm + g) * QSTR + ni * 8 + 2 * t]) =
                    __floats2half2_rn(p0, p1);
                *reinterpret_cast<__half2*>(&sP[(wm + g + 8) * QSTR + ni * 8 + 2 * t]) =
                    __floats2half2_rn(p2, p3);
            }
            lt0 += __shfl_xor_sync(0xffffffffu, lt0, 1);
            lt0 += __shfl_xor_sync(0xffffffffu, lt0, 2);
            lt1 += __shfl_xor_sync(0xffffffffu, lt1, 1);
            lt1 += __shfl_xor_sync(0xffffffffu, lt1, 2);
            l0 = l0 * al0 + lt0;
            l1 = l1 * al1 + lt1;

#pragma unroll
            for (int ni = 0; ni < 8; ni++) {
                accO[ni][0] *= al0; accO[ni][1] *= al0;
                accO[ni][2] *= al1; accO[ni][3] *= al1;
            }
            __syncwarp();   // sP rows are warp-private

            // ---- O += P @ V ----
#pragma unroll
            for (int ks = 0; ks < 4; ks++) {
                uint32_t pf[4];
                {
                    const uint32_t a = smu +
                        (uint32_t)(SP_OFF * 2) +
                        (uint32_t)((wm + arow_l) * QSTR + ks * 16 + akoff) * 2u;
                    LDSM_X4(pf[0], pf[1], pf[2], pf[3], a);
                }
#pragma unroll
                for (int pi = 0; pi < 4; pi++) {
                    const uint32_t a = vBase +
                        (uint32_t)((ks * 16 + vtrow) * QSTR + pi * 16 + vncol) * 2u;
                    uint32_t r0, r1, r2, r3;
                    LDSM_X4_T(r0, r1, r2, r3, a);
                    uint32_t bf0[2] = { r0, r1 }, bf1[2] = { r2, r3 };
                    mma_f16(accO[2 * pi],     pf, bf0);
                    mma_f16(accO[2 * pi + 1], pf, bf1);
                }
            }
            __syncwarp();   // done reading sP before next sub-tile overwrites it
        }
    }

    const float inv0 = 1.f / l0;
    const float inv1 = 1.f / l1;
#pragma unroll
    for (int ni = 0; ni < 8; ni++) {
        const int col = colbase + ni * 8 + 2 * t;
        *reinterpret_cast<__half2*>(&O[(rowbase + q0 + wm + g) * DIM + col]) =
            __floats2half2_rn(accO[ni][0] * inv0, accO[ni][1] * inv0);
        *reinterpret_cast<__half2*>(&O[(rowbase + q0 + wm + g + 8) * DIM + col]) =
            __floats2half2_rn(accO[ni][2] * inv1, accO[ni][3] * inv1);
    }
}

// ===========================================================================
extern "C" void kernel_launch(void* const* d_in, const int* in_sizes, int n_in,
                              void* d_out, int out_size)
{
    const float* x  = (const float*)d_in[0];
    const float* Wq = (const float*)d_in[1];
    const float* bq = (const float*)d_in[2];
    const float* Wk = (const float*)d_in[3];
    const float* bk = (const float*)d_in[4];
    const float* Wv = (const float*)d_in[5];
    const float* bv = (const float*)d_in[6];
    const float* Wo = (const float*)d_in[7];
    const float* bo = (const float*)d_in[8];
    float* out = (float*)d_out;

    __half *xh, *wh, *qh, *kh, *vh, *ctxh;
    cudaGetSymbolAddress((void**)&xh,   g_xh);
    cudaGetSymbolAddress((void**)&wh,   g_wh);
    cudaGetSymbolAddress((void**)&qh,   g_qh);
    cudaGetSymbolAddress((void**)&kh,   g_kh);
    cudaGetSymbolAddress((void**)&vh,   g_vh);
    cudaGetSymbolAddress((void**)&ctxh, g_ctxh);
    __half* wqh = wh;
    __half* wkh = wh + DIM * DIM;
    __half* wvh = wh + 2 * DIM * DIM;
    __half* woh = wh + 3 * DIM * DIM;

    // 1) fused prep: x and all W's -> fp16, one launch (z-split, MLP=4 x path)
    {
        dim3 pg(PREP_CHUNK / 256, 1, 5);
        f2h_multi_kernel<<<pg, 256>>>(
            (const float2*)x, (const float2*)Wq, (const float2*)Wk,
            (const float2*)Wv, (const float2*)Wo,
            (__half2*)xh, (__half2*)wh);
    }

    cudaFuncSetAttribute(gemm_h_kernel,
                         cudaFuncAttributeMaxDynamicSharedMemorySize,
                         GEMM_SMEM_BYTES);

    // 2) fused QKV projections (fp16 outputs)
    {
        dim3 gg(DIM / 128, NTOK / 128, 3);
        gemm_h_kernel<<<gg, 256, GEMM_SMEM_BYTES>>>(
            xh, wqh, wkh, wvh, bq, bk, bv, qh, kh, vh, 1);
    }

    // 3) attention (128-key staging, fp32 ex2 softmax)
    cudaFuncSetAttribute(attn_h_kernel,
                         cudaFuncAttributeMaxDynamicSharedMemorySize,
                         ATTN_SMEM_BYTES);
    attn_h_kernel<<<dim3(SEQ / 128, HEADS, BATCH), 256, ATTN_SMEM_BYTES>>>(
        qh, kh, vh, ctxh);

    // 4) output projection (fp32 output)
    {
        dim3 gg(DIM / 128, NTOK / 128, 1);
        gemm_h_kernel<<<gg, 256, GEMM_SMEM_BYTES>>>(
            ctxh, woh, woh, woh, bo, bo, bo, out, out, out, 0);
    }
}

// round 16
// speedup vs baseline: 1.0202x; 1.0001x over previous
#include <cuda_runtime.h>
#include <cuda_fp16.h>
#include <math_constants.h>
#include <cstdint>

#define NTOK 4096      // B*S
#define DIM  1024
#define HEADS 16
#define HDIM 64
#define SEQ  2048
#define BATCH 2

// Scratch (allocation-free requirement -> __device__ globals), all fp16
__device__ __half g_xh[NTOK * DIM];
__device__ __half g_wh[4 * DIM * DIM];    // fp16 Wq,Wk,Wv,Wo (natural [K][N])
__device__ __half g_qh[NTOK * DIM];
__device__ __half g_kh[NTOK * DIM];
__device__ __half g_vh[NTOK * DIM];
__device__ __half g_ctxh[NTOK * DIM];

// ===========================================================================
// Helpers
// ===========================================================================
__device__ __forceinline__ float ex2f(float x) {
    float y;
    asm("ex2.approx.ftz.f32 %0, %1;" : "=f"(y) : "f"(x));
    return y;
}

#define CP_ASYNC16(smem_addr, gmem_ptr) \
    asm volatile("cp.async.cg.shared.global [%0], [%1], 16;" \
                 :: "r"((uint32_t)(smem_addr)), "l"(gmem_ptr) : "memory")
#define CP_COMMIT() asm volatile("cp.async.commit_group;" ::: "memory")
#define CP_WAIT(n)  asm volatile("cp.async.wait_group %0;" :: "n"(n) : "memory")

__device__ __forceinline__ uint32_t smem_u32(const void* p) {
    uint32_t a;
    asm("{ .reg .u64 t; cvta.to.shared.u64 t, %1; cvt.u32.u64 %0, t; }"
        : "=r"(a) : "l"(p));
    return a;
}

#define LDSM_X4(r0, r1, r2, r3, addr) \
    asm volatile("ldmatrix.sync.aligned.m8n8.x4.shared.b16 {%0,%1,%2,%3}, [%4];" \
                 : "=r"(r0), "=r"(r1), "=r"(r2), "=r"(r3) : "r"(addr))

#define LDSM_X4_T(r0, r1, r2, r3, addr) \
    asm volatile("ldmatrix.sync.aligned.m8n8.x4.trans.shared.b16 {%0,%1,%2,%3}, [%4];" \
                 : "=r"(r0), "=r"(r1), "=r"(r2), "=r"(r3) : "r"(addr))

// mma m16n8k16 fp16 in, fp32 accum
__device__ __forceinline__ void mma_f16(
    float* d, const uint32_t* a, const uint32_t* b)
{
    asm volatile(
        "mma.sync.aligned.m16n8k16.row.col.f32.f16.f16.f32 "
        "{%0,%1,%2,%3}, {%4,%5,%6,%7}, {%8,%9}, {%0,%1,%2,%3};"
        : "+f"(d[0]), "+f"(d[1]), "+f"(d[2]), "+f"(d[3])
        : "r"(a[0]), "r"(a[1]), "r"(a[2]), "r"(a[3]),
          "r"(b[0]), "r"(b[1]));
}

// ===========================================================================
// fp16 GEMM:  C[z] = A @ W[z] + bias[z]
//  A:[4096,1024] fp16 row-major;  W:[K][N] fp16 natural layout via
//  ldmatrix.trans.  CTA tile 128x128, BK=64, 256 thr (8 warps of 32x64),
//  3-stage cp.async ring (CP_WAIT(1)), 2 CTAs/SM.  load_stage after the MMA
//  block (measured faster than hoisting at 2 CTAs/SM).
// ===========================================================================
#define GDIM 1024
#define BKH 64
#define ASTRH 72
#define BSTRH 136
#define A_STH (128 * ASTRH)          // 9216 halves
#define B_STH (BKH * BSTRH)          // 8704 halves
#define STH   (A_STH + B_STH)        // 17920 halves per stage
#define NSTG  3
#define GEMM_SMEM_BYTES (NSTG * STH * 2)   // 107520 B

__global__ void __launch_bounds__(256, 2) gemm_h_kernel(
    const __half* __restrict__ A,
    const __half* __restrict__ W0, const __half* __restrict__ W1,
    const __half* __restrict__ W2,
    const float* __restrict__ b0p, const float* __restrict__ b1p,
    const float* __restrict__ b2p,
    void* __restrict__ C0, void* __restrict__ C1, void* __restrict__ C2,
    int out_half)
{
    extern __shared__ __align__(16) __half smh[];

    const int z = blockIdx.z;
    const __half* W    = (z == 0) ? W0 : (z == 1) ? W1 : W2;
    const float*  bias = (z == 0) ? b0p : (z == 1) ? b1p : b2p;
    void*         Cv   = (z == 0) ? C0 : (z == 1) ? C1 : C2;

    const int tid  = threadIdx.x;
    const int wid  = tid >> 5;
    const int lane = tid & 31;
    const int g    = lane >> 2;
    const int t    = lane & 3;
    const int lrow = lane & 7;
    const int sub  = lane >> 3;      // 0..3
    const int wm   = wid >> 1;       // 0..3
    const int wn   = wid & 1;        // 0..1

    const int brow = blockIdx.y * 128;
    const int bcol = blockIdx.x * 128;

    const uint32_t smu = smem_u32(smh);

    const int arow_l = wm * 32 + lrow + ((sub & 1) << 3);
    const int akoff  = (sub >> 1) << 3;
    const int btrow  = lrow + ((sub & 1) << 3);
    const int bncol  = (sub >> 1) << 3;

    const int alr = tid >> 3;
    const int alc = (tid & 7) * 8;
    const __half* Asrc = A + (size_t)(brow + alr) * GDIM + alc;
    const int blr = tid >> 4;
    const int blc = (tid & 15) * 8;

    auto load_stage = [&](int s, int kt) {
        const int k0 = kt * BKH;
        const uint32_t abase = smu + (uint32_t)(s * STH) * 2u;
        const uint32_t bbase = abase + (uint32_t)A_STH * 2u;
#pragma unroll
        for (int i = 0; i < 4; i++) {
            const int ra = alr + i * 32;
            CP_ASYNC16(abase + (uint32_t)(ra * ASTRH + alc) * 2u,
                       Asrc + (size_t)(i * 32) * GDIM + k0);
            const int rb = blr + i * 16;
            CP_ASYNC16(bbase + (uint32_t)(rb * BSTRH + blc) * 2u,
                       W + (size_t)(k0 + rb) * GDIM + bcol + blc);
        }
        CP_COMMIT();
    };

    float acc[2][8][4];
#pragma unroll
    for (int mi = 0; mi < 2; mi++)
#pragma unroll
        for (int ni = 0; ni < 8; ni++)
#pragma unroll
            for (int c = 0; c < 4; c++) acc[mi][ni][c] = 0.f;

    load_stage(0, 0);
    load_stage(1, 1);

    const int NKT = GDIM / BKH;   // 16
    for (int kt = 0; kt < NKT; ++kt) {
        const int cur = kt % NSTG;
        CP_WAIT(1);
        __syncthreads();

        const uint32_t aBase = smu + (uint32_t)(cur * STH) * 2u;
        const uint32_t bBase = aBase + (uint32_t)A_STH * 2u;

#pragma unroll
        for (int ks = 0; ks < 4; ks++) {
            uint32_t af[2][4];
#pragma unroll
            for (int mi = 0; mi < 2; mi++) {
                const uint32_t a = aBase +
                    (uint32_t)((arow_l + mi * 16) * ASTRH + ks * 16 + akoff) * 2u;
                LDSM_X4(af[mi][0], af[mi][1], af[mi][2], af[mi][3], a);
            }
            uint32_t bf[8][2];
#pragma unroll
            for (int pi = 0; pi < 4; pi++) {
                const uint32_t a = bBase +
                    (uint32_t)((ks * 16 + btrow) * BSTRH +
                               wn * 64 + pi * 16 + bncol) * 2u;
                uint32_t r0, r1, r2, r3;
                LDSM_X4_T(r0, r1, r2, r3, a);
                bf[2 * pi][0] = r0; bf[2 * pi][1] = r1;
                bf[2 * pi + 1][0] = r2; bf[2 * pi + 1][1] = r3;
            }
#pragma unroll
            for (int mi = 0; mi < 2; mi++)
#pragma unroll
                for (int ni = 0; ni < 8; ni++)
                    mma_f16(acc[mi][ni], af[mi], bf[ni]);
        }

        if (kt + 2 < NKT) load_stage((kt + 2) % NSTG, kt + 2);
    }

    // Epilogue
#pragma unroll
    for (int ni = 0; ni < 8; ni++) {
        const int col = bcol + wn * 64 + ni * 8 + t * 2;
        const float2 bv = *reinterpret_cast<const float2*>(&bias[col]);
#pragma unroll
        for (int mi = 0; mi < 2; mi++) {
            const int r0 = brow + wm * 32 + mi * 16 + g;
            float2 v0, v1;
            v0.x = acc[mi][ni][0] + bv.x;
            v0.y = acc[mi][ni][1] + bv.y;
            v1.x = acc[mi][ni][2] + bv.x;
            v1.y = acc[mi][ni][3] + bv.y;
            if (out_half) {
                __half* C = (__half*)Cv;
                *reinterpret_cast<__half2*>(&C[(size_t)r0 * GDIM + col]) =
                    __floats2half2_rn(v0.x, v0.y);
                *reinterpret_cast<__half2*>(&C[(size_t)(r0 + 8) * GDIM + col]) =
                    __floats2half2_rn(v1.x, v1.y);
            } else {
                float* C = (float*)Cv;
                *reinterpret_cast<float2*>(&C[(size_t)r0 * GDIM + col])       = v0;
                *reinterpret_cast<float2*>(&C[(size_t)(r0 + 8) * GDIM + col]) = v1;
            }
        }
    }
}

// ===========================================================================
// Prep (z-split: z<4 -> W[z], z=4 -> x with 4 chunks/thread for MLP=4;
// measured fastest variant).
// ===========================================================================
#define PREP_CHUNK (DIM * DIM / 2)   // 524288 half2 per W

__global__ void f2h_multi_kernel(
    const float2* __restrict__ x,
    const float2* __restrict__ Wq, const float2* __restrict__ Wk,
    const float2* __restrict__ Wv, const float2* __restrict__ Wo,
    __half2* __restrict__ xh, __half2* __restrict__ wh)
{
    const int z = blockIdx.z;
    const int i = blockIdx.x * blockDim.x + threadIdx.x;
    if (z < 4) {
        const float2* src = (z == 0) ? Wq : (z == 1) ? Wk : (z == 2) ? Wv : Wo;
        float2 v = src[i];
        wh[(size_t)z * PREP_CHUNK + i] = __floats2half2_rn(v.x, v.y);
    } else {
#pragma unroll
        for (int j = 0; j < 4; j++) {
            const size_t idx = (size_t)i + (size_t)j * PREP_CHUNK;
            float2 v = x[idx];
            xh[idx] = __floats2half2_rn(v.x, v.y);
        }
    }
}

// ===========================================================================
// fp16 flash attention: 128-key K/V staging (two sequential 64-key
// sub-tiles), double-buffered, ldmatrix(+trans) fragments, fp32 ex2 softmax.
// Smem: sQ 128x72 + sP 128x72 + K 2x128x72 + V 2x128x72 = 110592 B; 2 CTAs/SM.
// ===========================================================================
#define QSTR 72
#define SP_OFF   (128 * QSTR)
#define SK_OFF   (2 * 128 * QSTR)
#define KVBUF    (128 * QSTR)                 // one 128-key buffer
#define SV_OFF   (SK_OFF + 2 * KVBUF)
#define ATTN_SMEM_BYTES ((2 * 128 * QSTR + 4 * KVBUF) * 2)   // 110592 B

__global__ void __launch_bounds__(256, 2) attn_h_kernel(
    const __half* __restrict__ Q, const __half* __restrict__ K,
    const __half* __restrict__ V, __half* __restrict__ O)
{
    extern __shared__ __align__(16) __half smh[];
    const uint32_t smu = smem_u32(smh);
    __half* sP = smh + SP_OFF;

    const int tid  = threadIdx.x;
    const int wid  = tid >> 5;
    const int lane = tid & 31;
    const int g    = lane >> 2;
    const int t    = lane & 3;
    const int lrow = lane & 7;
    const int sub  = lane >> 3;
    const int wm   = wid * 16;

    const int q0 = blockIdx.x * 128;
    const int h  = blockIdx.y;
    const int b  = blockIdx.z;
    const size_t rowbase = (size_t)b * SEQ;
    const int colbase = h * HDIM;

    const float cscale = 0.125f * 1.4426950408889634f;  // 1/sqrt(64)*log2(e)

    const int arow_l = lrow + ((sub & 1) << 3);
    const int akoff  = (sub >> 1) << 3;
    const int bn_l   = lrow + ((sub >> 1) << 3);
    const int bkoff  = (sub & 1) << 3;
    const int vtrow  = lrow + ((sub & 1) << 3);
    const int vncol  = (sub >> 1) << 3;

    // ---- stage Q ----
    {
        const int qr  = tid >> 1;
        const int qc  = (tid & 1) * 32;
        const __half* src = &Q[(rowbase + q0 + qr) * DIM + colbase + qc];
        const uint32_t dst = smu + (uint32_t)(qr * QSTR + qc) * 2u;
#pragma unroll
        for (int i = 0; i < 4; i++)
            CP_ASYNC16(dst + i * 16, src + i * 8);
    }

    // K/V loader: 128 rows x 64 halves each; per thread rows kr, kr+64,
    // 2 chunks per row per operand.
    const int kr = tid >> 2;                 // 0..63
    const int kc = (tid & 3) * 16;
    auto load_kv = [&](int s, int t0) {
        const uint32_t kb = smu + (uint32_t)(SK_OFF + s * KVBUF) * 2u;
        const uint32_t vb = smu + (uint32_t)(SV_OFF + s * KVBUF) * 2u;
#pragma unroll
        for (int i = 0; i < 2; i++) {
            const int r = kr + i * 64;
            const uint32_t off = (uint32_t)(r * QSTR + kc) * 2u;
            const __half* ksrc = &K[(rowbase + t0 + r) * DIM + colbase + kc];
            const __half* vsrc = &V[(rowbase + t0 + r) * DIM + colbase + kc];
            CP_ASYNC16(kb + off,      ksrc);
            CP_ASYNC16(kb + off + 16, ksrc + 8);
            CP_ASYNC16(vb + off,      vsrc);
            CP_ASYNC16(vb + off + 16, vsrc + 8);
        }
        CP_COMMIT();
    };

    load_kv(0, 0);   // commits Q loads too

    float m0 = -CUDART_INF_F, m1 = -CUDART_INF_F;
    float l0 = 0.f, l1 = 0.f;
    float accO[8][4];
#pragma unroll
    for (int ni = 0; ni < 8; ni++)
#pragma unroll
        for (int c = 0; c < 4; c++) accO[ni][c] = 0.f;

    for (int t0 = 0; t0 < SEQ; t0 += 128) {
        const int cur = (t0 >> 7) & 1;
        CP_WAIT(0);
        __syncthreads();
        if (t0 + 128 < SEQ) load_kv(cur ^ 1, t0 + 128);

#pragma unroll
        for (int hf = 0; hf < 2; hf++) {
            const uint32_t kBase = smu +
                (uint32_t)(SK_OFF + cur * KVBUF + hf * 64 * QSTR) * 2u;
            const uint32_t vBase = smu +
                (uint32_t)(SV_OFF + cur * KVBUF + hf * 64 * QSTR) * 2u;

            // ---- S = Q @ K^T (fp32 accum) ----
            float sfr[8][4];
#pragma unroll
            for (int ni = 0; ni < 8; ni++)
#pragma unroll
                for (int c = 0; c < 4; c++) sfr[ni][c] = 0.f;

#pragma unroll
            for (int ks = 0; ks < 4; ks++) {
                uint32_t af[4];
                {
                    const uint32_t a = smu +
                        (uint32_t)((wm + arow_l) * QSTR + ks * 16 + akoff) * 2u;
                    LDSM_X4(af[0], af[1], af[2], af[3], a);
                }
#pragma unroll
                for (int pi = 0; pi < 4; pi++) {
                    const uint32_t a = kBase +
                        (uint32_t)((bn_l + pi * 16) * QSTR + ks * 16 + bkoff) * 2u;
                    uint32_t r0, r1, r2, r3;
                    LDSM_X4(r0, r1, r2, r3, a);
                    uint32_t bf0[2] = { r0, r1 }, bf1[2] = { r2, r3 };
                    mma_f16(sfr[2 * pi],     af, bf0);
                    mma_f16(sfr[2 * pi + 1], af, bf1);
                }
            }

            // ---- online softmax (fp32 ex2) ----
            float mt0 = sfr[0][0], mt1 = sfr[0][2];
#pragma unroll
            for (int ni = 0; ni < 8; ni++) {
                mt0 = fmaxf(mt0, fmaxf(sfr[ni][0], sfr[ni][1]));
                mt1 = fmaxf(mt1, fmaxf(sfr[ni][2], sfr[ni][3]));
            }
            mt0 = fmaxf(mt0, __shfl_xor_sync(0xffffffffu, mt0, 1));
            mt0 = fmaxf(mt0, __shfl_xor_sync(0xffffffffu, mt0, 2));
            mt1 = fmaxf(mt1, __shfl_xor_sync(0xffffffffu, mt1, 1));
            mt1 = fmaxf(mt1, __shfl_xor_sync(0xffffffffu, mt1, 2));
            mt0 *= cscale;
            mt1 *= cscale;

            const float mn0 = fmaxf(m0, mt0);
            const float mn1 = fmaxf(m1, mt1);
            const float al0 = ex2f(m0 - mn0);
            const float al1 = ex2f(m1 - mn1);
            m0 = mn0; m1 = mn1;

            float lt0 = 0.f, lt1 = 0.f;
#pragma unroll
            for (int ni = 0; ni < 8; ni++) {
                float p0 = ex2f(sfr[ni][0] * cscale - mn0);
                float p1 = ex2f(sfr[ni][1] * cscale - mn0);
                float p2 = ex2f(sfr[ni][2] * cscale - mn1);
                float p3 = ex2f(sfr[ni][3] * cscale - mn1);
                lt0 += p0 + p1;
                lt1 += p2 + p3;
                *reinterpret_cast<__half2*>(&sP[(wm + g) * QSTR + ni * 8 + 2 * t]) =
                    __floats2half2_rn(p0, p1);
                *reinterpret_cast<__half2*>(&sP[(wm + g + 8) * QSTR + ni * 8 + 2 * t]) =
                    __floats2half2_rn(p2, p3);
            }
            lt0 += __shfl_xor_sync(0xffffffffu, lt0, 1);
            lt0 += __shfl_xor_sync(0xffffffffu, lt0, 2);
            lt1 += __shfl_xor_sync(0xffffffffu, lt1, 1);
            lt1 += __shfl_xor_sync(0xffffffffu, lt1, 2);
            l0 = l0 * al0 + lt0;
            l1 = l1 * al1 + lt1;

#pragma unroll
            for (int ni = 0; ni < 8; ni++) {
                accO[ni][0] *= al0; accO[ni][1] *= al0;
                accO[ni][2] *= al1; accO[ni][3] *= al1;
            }
            __syncwarp();   // sP rows are warp-private

            // ---- O += P @ V ----
#pragma unroll
            for (int ks = 0; ks < 4; ks++) {
                uint32_t pf[4];
                {
                    const uint32_t a = smu +
                        (uint32_t)(SP_OFF * 2) +
                        (uint32_t)((wm + arow_l) * QSTR + ks * 16 + akoff) * 2u;
                    LDSM_X4(pf[0], pf[1], pf[2], pf[3], a);
                }
#pragma unroll
                for (int pi = 0; pi < 4; pi++) {
                    const uint32_t a = vBase +
                        (uint32_t)((ks * 16 + vtrow) * QSTR + pi * 16 + vncol) * 2u;
                    uint32_t r0, r1, r2, r3;
                    LDSM_X4_T(r0, r1, r2, r3, a);
                    uint32_t bf0[2] = { r0, r1 }, bf1[2] = { r2, r3 };
                    mma_f16(accO[2 * pi],     pf, bf0);
                    mma_f16(accO[2 * pi + 1], pf, bf1);
                }
            }
            __syncwarp();   // done reading sP before next sub-tile overwrites it
        }
    }

    const float inv0 = 1.f / l0;
    const float inv1 = 1.f / l1;
#pragma unroll
    for (int ni = 0; ni < 8; ni++) {
        const int col = colbase + ni * 8 + 2 * t;
        *reinterpret_cast<__half2*>(&O[(rowbase + q0 + wm + g) * DIM + col]) =
            __floats2half2_rn(accO[ni][0] * inv0, accO[ni][1] * inv0);
        *reinterpret_cast<__half2*>(&O[(rowbase + q0 + wm + g + 8) * DIM + col]) =
            __floats2half2_rn(accO[ni][2] * inv1, accO[ni][3] * inv1);
    }
}

// ===========================================================================
extern "C" void kernel_launch(void* const* d_in, const int* in_sizes, int n_in,
                              void* d_out, int out_size)
{
    const float* x  = (const float*)d_in[0];
    const float* Wq = (const float*)d_in[1];
    const float* bq = (const float*)d_in[2];
    const float* Wk = (const float*)d_in[3];
    const float* bk = (const float*)d_in[4];
    const float* Wv = (const float*)d_in[5];
    const float* bv = (const float*)d_in[6];
    const float* Wo = (const float*)d_in[7];
    const float* bo = (const float*)d_in[8];
    float* out = (float*)d_out;

    __half *xh, *wh, *qh, *kh, *vh, *ctxh;
    cudaGetSymbolAddress((void**)&xh,   g_xh);
    cudaGetSymbolAddress((void**)&wh,   g_wh);
    cudaGetSymbolAddress((void**)&qh,   g_qh);
    cudaGetSymbolAddress((void**)&kh,   g_kh);
    cudaGetSymbolAddress((void**)&vh,   g_vh);
    cudaGetSymbolAddress((void**)&ctxh, g_ctxh);
    __half* wqh = wh;
    __half* wkh = wh + DIM * DIM;
    __half* wvh = wh + 2 * DIM * DIM;
    __half* woh = wh + 3 * DIM * DIM;

    // 1) fused prep: x and all W's -> fp16, one launch (z-split, MLP=4 x path)
    {
        dim3 pg(PREP_CHUNK / 256, 1, 5);
        f2h_multi_kernel<<<pg, 256>>>(
            (const float2*)x, (const float2*)Wq, (const float2*)Wk,
            (const float2*)Wv, (const float2*)Wo,
            (__half2*)xh, (__half2*)wh);
    }

    cudaFuncSetAttribute(gemm_h_kernel,
                         cudaFuncAttributeMaxDynamicSharedMemorySize,
                         GEMM_SMEM_BYTES);

    // 2) fused QKV projections (fp16 outputs)
    {
        dim3 gg(DIM / 128, NTOK / 128, 3);
        gemm_h_kernel<<<gg, 256, GEMM_SMEM_BYTES>>>(
            xh, wqh, wkh, wvh, bq, bk, bv, qh, kh, vh, 1);
    }

    // 3) attention (128-key staging, fp32 ex2 softmax)
    cudaFuncSetAttribute(attn_h_kernel,
                         cudaFuncAttributeMaxDynamicSharedMemorySize,
                         ATTN_SMEM_BYTES);
    attn_h_kernel<<<dim3(SEQ / 128, HEADS, BATCH), 256, ATTN_SMEM_BYTES>>>(
        qh, kh, vh, ctxh);

    // 4) output projection (fp32 output)
    {
        dim3 gg(DIM / 128, NTOK / 128, 1);
        gemm_h_kernel<<<gg, 256, GEMM_SMEM_BYTES>>>(
            ctxh, woh, woh, woh, bo, bo, bo, out, out, out, 0);
    }
}